// round 14
// baseline (speedup 1.0000x reference)
#include <cuda_runtime.h>
#include <cstdint>

#define NPTS   4096
#define EMB    768
#define QKVW   2304
#define KCL    64
#define THRESH 1e-4f
#define DKMEPS 1e-6f
#define LNEPS  1e-5f
#define NB     148      // persistent grid size (<= SM count, 1 CTA/SM guaranteed)

#define LOG2E  1.44269504088896f

// ---------------- scratch (static device globals; no allocation) ----------------
__device__ float g_bufA[NPTS * EMB];
__device__ float g_QKV [NPTS * QKVW];
__device__ float g_bufB[NPTS * EMB];
__device__ float g_X   [NPTS * EMB];
__device__ float g_Xhi [NPTS * EMB];
__device__ float g_Xlo [NPTS * EMB];
__device__ float g_xsq [NPTS];
__device__ float g_Cprev[KCL * EMB];
__device__ float g_Chi [KCL * EMB];
__device__ float g_Clo [KCL * EMB];
__device__ float g_Cpart[16 * KCL * EMB];     // split-N partials of a^T X
__device__ float g_asum_part[128 * KCL];      // per-assign-tile partials of sum_n a[n,k]
__device__ float g_csqp[192];                 // per-chunk partials of |c_k|^2
__device__ float g_diffp[192];                // per-chunk partials of sum|dC|
__device__ unsigned g_bar_gen;
__device__ unsigned g_bar_cnt;

// ---------------- FMA-pipe exp2 (no MUFU): deg-6 poly, ~1e-7 rel ----------------
__device__ __forceinline__ float exp2p(float x) {
    x = fmaxf(x, -120.f);
    float t  = x + 12582912.f;                  // 1.5*2^23
    int   ei = __float_as_int(t);
    float xi = t - 12582912.f;
    float f  = x - xi;                          // [-0.5, 0.5]
    float p  = 1.53996129e-4f;
    p = fmaf(p, f, 1.33335581e-3f);
    p = fmaf(p, f, 9.61812910e-3f);
    p = fmaf(p, f, 5.55041086e-2f);
    p = fmaf(p, f, 2.40226512e-1f);
    p = fmaf(p, f, 6.93147182e-1f);
    p = fmaf(p, f, 1.0f);
    float s = __int_as_float((ei + 127) << 23);
    return p * s;
}

// ---------------- tf32 helpers ----------------
__device__ __forceinline__ uint32_t f2tf32(float f) {
    uint32_t u;
    asm("cvt.rna.tf32.f32 %0, %1;" : "=r"(u) : "f"(f));
    return u;
}
__device__ __forceinline__ float tf32r(float f) {
    return __uint_as_float(f2tf32(f));
}
__device__ __forceinline__ uint32_t fu(float f) { return __float_as_uint(f); }
__device__ __forceinline__ void mma_tf32(float* d, const uint32_t* a, const uint32_t* b) {
    asm volatile(
        "mma.sync.aligned.m16n8k8.row.col.f32.tf32.tf32.f32 "
        "{%0,%1,%2,%3}, {%4,%5,%6,%7}, {%8,%9}, {%0,%1,%2,%3};"
        : "+f"(d[0]), "+f"(d[1]), "+f"(d[2]), "+f"(d[3])
        : "r"(a[0]), "r"(a[1]), "r"(a[2]), "r"(a[3]), "r"(b[0]), "r"(b[1]));
}

// ---------------- helpers ----------------
template<int NW>
__device__ __forceinline__ float blockSum(float v, float* red) {
    #pragma unroll
    for (int o = 16; o; o >>= 1) v += __shfl_xor_sync(0xffffffffu, v, o);
    int t = threadIdx.x;
    if ((t & 31) == 0) red[t >> 5] = v;
    __syncthreads();
    float s = 0.f;
    #pragma unroll
    for (int w = 0; w < NW; w++) s += red[w];
    __syncthreads();
    return s;
}

// two-channel block sum; per-channel arithmetic order identical to blockSum<8>
__device__ __forceinline__ float2 blockSum2(float a, float b, float2* red2) {
    #pragma unroll
    for (int o = 16; o; o >>= 1) {
        a += __shfl_xor_sync(0xffffffffu, a, o);
        b += __shfl_xor_sync(0xffffffffu, b, o);
    }
    int t = threadIdx.x;
    if ((t & 31) == 0) red2[t >> 5] = make_float2(a, b);
    __syncthreads();
    float sa = 0.f, sb = 0.f;
    #pragma unroll
    for (int w = 0; w < 8; w++) { sa += red2[w].x; sb += red2[w].y; }
    __syncthreads();
    return make_float2(sa, sb);
}

// sense-reversing grid barrier; safe because grid == NB and all CTAs resident
__device__ __forceinline__ void gridbar() {
    __syncthreads();
    if (threadIdx.x == 0) {
        unsigned gen = *(volatile unsigned*)&g_bar_gen;
        __threadfence();
        if (atomicAdd(&g_bar_cnt, 1u) == NB - 1) {
            g_bar_cnt = 0;
            __threadfence();
            *(volatile unsigned*)&g_bar_gen = gen + 1;
        } else {
            while (*(volatile unsigned*)&g_bar_gen == gen) { __nanosleep(32); }
        }
        __threadfence();
    }
    __syncthreads();
}

// ======== tensor-core GEMM (tf32 mma): OUT[M,N] = act(A[M,K] @ W[N,K]^T + b) =======
#define TG_SMEM ((2*128*36 + 2*64*36) * 4)
template<bool RELU>
__global__ void __launch_bounds__(256) tgemm(
    const float* __restrict__ A, const float* __restrict__ W,
    const float* __restrict__ bias, float* __restrict__ OUT,
    int Nn, int Kd)
{
    extern __shared__ float smem[];
    float* sA[2] = { smem, smem + 128*36 };
    float* sB[2] = { smem + 2*128*36, smem + 2*128*36 + 64*36 };

    const int t    = threadIdx.x;
    const int lane = t & 31;
    const int wid  = t >> 5;
    const int lr   = lane >> 2;
    const int lc   = lane & 3;
    const int wr0  = (wid >> 1) * 32;
    const int wc0  = (wid & 1) * 32;
    const int row0 = blockIdx.y * 128;
    const int col0 = blockIdx.x * 64;

    float d[2][4][4] = {};
    float4 ra[4]; float4 rb[2];

    auto gload = [&](int s) {
        const int k0 = s << 5;
        #pragma unroll
        for (int i = 0; i < 4; i++) {
            int lin = t + (i << 8);
            int r = lin >> 3, c = (lin & 7) << 2;
            ra[i] = *(const float4*)&A[(size_t)(row0 + r) * Kd + k0 + c];
        }
        #pragma unroll
        for (int i = 0; i < 2; i++) {
            int lin = t + (i << 8);
            int n = lin >> 3, c = (lin & 7) << 2;
            rb[i] = *(const float4*)&W[(size_t)(col0 + n) * Kd + k0 + c];
        }
    };
    auto sstore = [&](int buf) {
        #pragma unroll
        for (int i = 0; i < 4; i++) {
            int lin = t + (i << 8);
            int r = lin >> 3, c = (lin & 7) << 2;
            float* p = &sA[buf][r * 36 + c];
            p[0] = tf32r(ra[i].x); p[1] = tf32r(ra[i].y);
            p[2] = tf32r(ra[i].z); p[3] = tf32r(ra[i].w);
        }
        #pragma unroll
        for (int i = 0; i < 2; i++) {
            int lin = t + (i << 8);
            int n = lin >> 3, c = (lin & 7) << 2;
            float* p = &sB[buf][n * 36 + c];
            p[0] = tf32r(rb[i].x); p[1] = tf32r(rb[i].y);
            p[2] = tf32r(rb[i].z); p[3] = tf32r(rb[i].w);
        }
    };

    gload(0); sstore(0);
    __syncthreads();

    const int nslab = Kd >> 5;
    for (int s = 0; s < nslab; s++) {
        const int cur = s & 1;
        const bool more = (s + 1 < nslab);
        if (more) gload(s + 1);
        #pragma unroll
        for (int ks = 0; ks < 32; ks += 8) {
            uint32_t af[2][4], bf[4][2];
            #pragma unroll
            for (int mt = 0; mt < 2; mt++) {
                const float* p = &sA[cur][(wr0 + mt*16 + lr) * 36 + ks + lc];
                af[mt][0] = fu(p[0]);
                af[mt][1] = fu(p[8*36]);
                af[mt][2] = fu(p[4]);
                af[mt][3] = fu(p[8*36 + 4]);
            }
            #pragma unroll
            for (int nt = 0; nt < 4; nt++) {
                const float* p = &sB[cur][(wc0 + nt*8 + lr) * 36 + ks + lc];
                bf[nt][0] = fu(p[0]);
                bf[nt][1] = fu(p[4]);
            }
            #pragma unroll
            for (int mt = 0; mt < 2; mt++)
                #pragma unroll
                for (int nt = 0; nt < 4; nt++)
                    mma_tf32(d[mt][nt], af[mt], bf[nt]);
        }
        if (more) {
            sstore(cur ^ 1);
            __syncthreads();
        }
    }

    #pragma unroll
    for (int mt = 0; mt < 2; mt++) {
        #pragma unroll
        for (int nt = 0; nt < 4; nt++) {
            int r0 = row0 + wr0 + mt*16 + lr;
            int c0 = col0 + wc0 + nt*8 + (lc << 1);
            float b0 = bias[c0], b1 = bias[c0 + 1];
            float v0 = d[mt][nt][0] + b0, v1 = d[mt][nt][1] + b1;
            float v2 = d[mt][nt][2] + b0, v3 = d[mt][nt][3] + b1;
            if (RELU) {
                v0 = fmaxf(v0, 0.f); v1 = fmaxf(v1, 0.f);
                v2 = fmaxf(v2, 0.f); v3 = fmaxf(v3, 0.f);
            }
            *(float2*)&OUT[(size_t)r0 * Nn + c0]       = make_float2(v0, v1);
            *(float2*)&OUT[(size_t)(r0 + 8) * Nn + c0] = make_float2(v2, v3);
        }
    }
}

// ========== flash attention mma: Q-tile 128, K-tile 128, hd=64, tf32 tensor =========
#define FLM_SMEM ((128*68 + 128*68 + 128*72 + 128*132) * 4)
__global__ void __launch_bounds__(256) flashm(
    const float* __restrict__ QKV, float* __restrict__ O)
{
    extern __shared__ float sm[];
    float* sQ = sm;                  // [q=128][d=64] stride 68 (tf32)
    float* sK = sQ + 128*68;         // [c=128][d=64] stride 68 (tf32)
    float* sV = sK + 128*68;         // [c=128][d=64] stride 72 (tf32)
    float* sP = sV + 128*72;         // [q=128][c=128] stride 132 (tf32)
    const int t    = threadIdx.x;
    const int lane = t & 31;
    const int w    = t >> 5;
    const int lr   = lane >> 2;
    const int lc   = lane & 3;
    const int qb   = blockIdx.x, h = blockIdx.y;
    const int q0   = w * 16;
    const float SC2 = 0.125f * LOG2E;

    {
        int r = t >> 1, half = t & 1;
        #pragma unroll
        for (int p = 0; p < 8; p++) {
            int d = half*32 + p*4;
            float4 q = *(const float4*)&QKV[(size_t)(qb*128 + r) * QKVW + h*64 + d];
            float* dq = &sQ[r*68 + d];
            dq[0] = tf32r(q.x); dq[1] = tf32r(q.y); dq[2] = tf32r(q.z); dq[3] = tf32r(q.w);
        }
    }

    float oacc[8][4] = {};
    float m[2] = {-1e30f, -1e30f}, l[2] = {0.f, 0.f};

    for (int kb = 0; kb < 32; kb++) {
        {
            int r = t >> 1, half = t & 1;
            #pragma unroll
            for (int p = 0; p < 8; p++) {
                int d = half*32 + p*4;
                float4 kv = *(const float4*)&QKV[(size_t)(kb*128 + r) * QKVW + 768 + h*64 + d];
                float* dk = &sK[r*68 + d];
                dk[0] = tf32r(kv.x); dk[1] = tf32r(kv.y); dk[2] = tf32r(kv.z); dk[3] = tf32r(kv.w);
                float4 vv = *(const float4*)&QKV[(size_t)(kb*128 + r) * QKVW + 1536 + h*64 + d];
                float* dv = &sV[r*72 + d];
                dv[0] = tf32r(vv.x); dv[1] = tf32r(vv.y); dv[2] = tf32r(vv.z); dv[3] = tf32r(vv.w);
            }
        }
        __syncthreads();

        float sacc[16][4] = {};
        #pragma unroll
        for (int kk = 0; kk < 8; kk++) {
            const int k0 = kk * 8;
            uint32_t a[4];
            const float* pa = &sQ[(q0 + lr)*68 + k0 + lc];
            a[0] = fu(pa[0]); a[1] = fu(pa[8*68]); a[2] = fu(pa[4]); a[3] = fu(pa[8*68 + 4]);
            #pragma unroll
            for (int nt = 0; nt < 16; nt++) {
                uint32_t b[2];
                const float* pb = &sK[(nt*8 + lr)*68 + k0 + lc];
                b[0] = fu(pb[0]); b[1] = fu(pb[4]);
                mma_tf32(sacc[nt], a, b);
            }
        }

        #pragma unroll
        for (int row = 0; row < 2; row++) {
            float mx = -1e30f;
            #pragma unroll
            for (int nt = 0; nt < 16; nt++) {
                sacc[nt][row*2]   *= SC2;
                sacc[nt][row*2+1] *= SC2;
                mx = fmaxf(mx, fmaxf(sacc[nt][row*2], sacc[nt][row*2+1]));
            }
            mx = fmaxf(mx, __shfl_xor_sync(0xffffffffu, mx, 1));
            mx = fmaxf(mx, __shfl_xor_sync(0xffffffffu, mx, 2));
            float mn = fmaxf(m[row], mx);
            float sc = exp2p(m[row] - mn);
            float ps = 0.f;
            #pragma unroll
            for (int nt = 0; nt < 16; nt++) {
                float e0 = exp2p(sacc[nt][row*2]   - mn);
                float e1 = exp2p(sacc[nt][row*2+1] - mn);
                sacc[nt][row*2] = e0; sacc[nt][row*2+1] = e1;
                ps += e0 + e1;
            }
            ps += __shfl_xor_sync(0xffffffffu, ps, 1);
            ps += __shfl_xor_sync(0xffffffffu, ps, 2);
            l[row] = l[row] * sc + ps;
            m[row] = mn;
            #pragma unroll
            for (int nd = 0; nd < 8; nd++) {
                oacc[nd][row*2]   *= sc;
                oacc[nd][row*2+1] *= sc;
            }
        }

        #pragma unroll
        for (int nt = 0; nt < 16; nt++) {
            int c = nt*8 + lc*2;
            *(float2*)&sP[(q0 + lr)*132 + c]     = make_float2(tf32r(sacc[nt][0]), tf32r(sacc[nt][1]));
            *(float2*)&sP[(q0 + lr + 8)*132 + c] = make_float2(tf32r(sacc[nt][2]), tf32r(sacc[nt][3]));
        }
        __syncthreads();

        #pragma unroll
        for (int kc = 0; kc < 16; kc++) {
            uint32_t a[4];
            const float* pa = &sP[(q0 + lr)*132 + kc*8 + lc];
            a[0] = fu(pa[0]); a[1] = fu(pa[8*132]); a[2] = fu(pa[4]); a[3] = fu(pa[8*132 + 4]);
            #pragma unroll
            for (int nd = 0; nd < 8; nd++) {
                uint32_t b[2];
                const float* pb = &sV[(kc*8 + lc)*72 + nd*8 + lr];
                b[0] = fu(pb[0]); b[1] = fu(pb[4*72]);
                mma_tf32(oacc[nd], a, b);
            }
        }
        __syncthreads();
    }

    const float inv0 = 1.f / l[0], inv1 = 1.f / l[1];
    #pragma unroll
    for (int nd = 0; nd < 8; nd++) {
        int r = qb*128 + q0 + lr;
        int c = h*64 + nd*8 + lc*2;
        *(float2*)&O[(size_t)r * EMB + c]       = make_float2(oacc[nd][0]*inv0, oacc[nd][1]*inv0);
        *(float2*)&O[(size_t)(r + 8) * EMB + c] = make_float2(oacc[nd][2]*inv1, oacc[nd][3]*inv1);
    }
}

// ---------------- residual + layernorm + xsq + X hi/lo ----------------
__global__ void __launch_bounds__(256) ln_kernel(
    const float* __restrict__ x0, const float* __restrict__ y,
    const float* __restrict__ lg, const float* __restrict__ lb)
{
    __shared__ float red[8];
    int r = blockIdx.x, t = threadIdx.x;
    float z[3];
    float s = 0.f;
    #pragma unroll
    for (int i = 0; i < 3; i++) {
        int c = t + i * 256;
        z[i] = 0.5f * x0[(size_t)r * EMB + c] + 0.5f * y[(size_t)r * EMB + c];
        s += z[i];
    }
    s = blockSum<8>(s, red);
    float mu = s * (1.f / 768.f);
    float v = 0.f;
    #pragma unroll
    for (int i = 0; i < 3; i++) { float dz = z[i] - mu; v = fmaf(dz, dz, v); }
    v = blockSum<8>(v, red);
    float rstd = rsqrtf(v * (1.f / 768.f) + LNEPS);
    float q = 0.f;
    #pragma unroll
    for (int i = 0; i < 3; i++) {
        int c = t + i * 256;
        float xv = (z[i] - mu) * rstd * lg[c] + lb[c];
        size_t gi = (size_t)r * EMB + c;
        g_X[gi] = xv;
        float hi = tf32r(xv);
        g_Xhi[gi] = hi;
        g_Xlo[gi] = tf32r(xv - hi);
        q = fmaf(xv, xv, q);
    }
    q = blockSum<8>(q, red);
    if (t == 0) g_xsq[r] = q;
}

// ================= persistent DKM: whole loop in ONE kernel ======================
// distances via 3xTF32 mma (err ~1e-6); softmax/eps/div math identical to reference
// phase A: 64-wide K slabs + register prefetch; phase B: register prefetch
#define DKM_SMEM ((2*32*68 + 2*64*68) * 4)     // 52224 B (phase A is the max)
__global__ void __launch_bounds__(256) dkm_persist(
    const int* __restrict__ idx, float* __restrict__ outC, float* __restrict__ outA)
{
    extern __shared__ float dsm[];
    __shared__ float red[8];
    __shared__ float2 red2[8];
    __shared__ float s_csq[64];
    __shared__ float s_m[32][4];
    __shared__ float s_s[32][4];
    __shared__ float s_as[64][2];

    const int b    = blockIdx.x;
    const int t    = threadIdx.x;
    const int lane = t & 31;
    const int w    = t >> 5;
    const int lr   = lane >> 2;
    const int lc   = lane & 3;

    // ---- init: gather C0 = X[idx] (+hi/lo), csq chunk partials ----
    for (int c = b; c < 192; c += NB) {
        int k = c / 3;
        int i = c * 256 + t;
        int e = i - k * EMB;
        float v = g_X[(size_t)idx[k] * EMB + e];
        outC[i] = v;
        float hi = tf32r(v);
        g_Chi[i] = hi;
        g_Clo[i] = tf32r(v - hi);
        float s = blockSum<8>(v * v, red);
        if (t == 0) g_csqp[c] = s;
    }
    gridbar();

    for (int it = 0; it <= 100; it++) {
        // ---- break check: parallel 192-way load + blockSum (identical in all blocks) ----
        if (it > 0) {
            float dv = (t < 192) ? g_diffp[t] : 0.f;
            float diff = blockSum<8>(dv, red);
            if (diff <= THRESH) {
                for (int c = b; c < 192; c += NB)
                    outC[c * 256 + t] = g_Cprev[c * 256 + t];
                return;
            }
        }

        // ---- phase A: assignments via 3xTF32 mma (blocks 0..127, 32 rows each) ----
        if (b < 128) {
            if (t < 64) s_csq[t] = g_csqp[3*t] + g_csqp[3*t+1] + g_csqp[3*t+2];
            const int row0 = b * 32;
            float* aXh = dsm;                    // [32][68]
            float* aXl = dsm + 32*68;
            float* aCh = dsm + 2*32*68;          // [64][68]
            float* aCl = dsm + 2*32*68 + 64*68;
            const int vr = w & 1, vc = w >> 1;   // 2 warp-rows x 4 warp-cols

            float dacc[2][4] = {};
            const int xr = t >> 3, xc = (t & 7) << 3;   // X: 32 rows, 8 thr/row, 8 cols each
            const int cr = t >> 2, cc = (t & 3) << 4;   // C: 64 rows, 4 thr/row, 16 cols each
            float4 pXh[2], pXl[2], pCh[4], pCl[4];

            auto loadA = [&](int ks) {
                size_t gx = (size_t)(row0 + xr) * EMB + ks*64 + xc;
                pXh[0] = *(const float4*)&g_Xhi[gx];
                pXh[1] = *(const float4*)&g_Xhi[gx + 4];
                pXl[0] = *(const float4*)&g_Xlo[gx];
                pXl[1] = *(const float4*)&g_Xlo[gx + 4];
                size_t gc = (size_t)cr * EMB + ks*64 + cc;
                #pragma unroll
                for (int i = 0; i < 4; i++) {
                    pCh[i] = *(const float4*)&g_Chi[gc + i*4];
                    pCl[i] = *(const float4*)&g_Clo[gc + i*4];
                }
            };
            auto storeA = [&]() {
                *(float4*)&aXh[xr*68 + xc]     = pXh[0];
                *(float4*)&aXh[xr*68 + xc + 4] = pXh[1];
                *(float4*)&aXl[xr*68 + xc]     = pXl[0];
                *(float4*)&aXl[xr*68 + xc + 4] = pXl[1];
                #pragma unroll
                for (int i = 0; i < 4; i++) {
                    *(float4*)&aCh[cr*68 + cc + i*4] = pCh[i];
                    *(float4*)&aCl[cr*68 + cc + i*4] = pCl[i];
                }
            };

            loadA(0); storeA();
            __syncthreads();
            for (int ks = 0; ks < 12; ks++) {
                const bool more = (ks + 1 < 12);
                if (more) loadA(ks + 1);
                #pragma unroll
                for (int kk = 0; kk < 8; kk++) {
                    const int k0 = kk * 8;
                    uint32_t ah[4], al[4];
                    const float* ph = &aXh[(vr*16 + lr)*68 + k0 + lc];
                    ah[0]=fu(ph[0]); ah[1]=fu(ph[8*68]); ah[2]=fu(ph[4]); ah[3]=fu(ph[8*68+4]);
                    const float* pl = &aXl[(vr*16 + lr)*68 + k0 + lc];
                    al[0]=fu(pl[0]); al[1]=fu(pl[8*68]); al[2]=fu(pl[4]); al[3]=fu(pl[8*68+4]);
                    #pragma unroll
                    for (int nf = 0; nf < 2; nf++) {
                        uint32_t bh[2], bl[2];
                        const float* qh = &aCh[(vc*16 + nf*8 + lr)*68 + k0 + lc];
                        bh[0]=fu(qh[0]); bh[1]=fu(qh[4]);
                        const float* ql = &aCl[(vc*16 + nf*8 + lr)*68 + k0 + lc];
                        bl[0]=fu(ql[0]); bl[1]=fu(ql[4]);
                        mma_tf32(dacc[nf], ah, bh);
                        mma_tf32(dacc[nf], ah, bl);
                        mma_tf32(dacc[nf], al, bh);
                    }
                }
                __syncthreads();            // done reading smem
                if (more) {
                    storeA();
                    __syncthreads();        // smem ready
                }
            }

            // epilogue: dist + softmax (formulas identical to reference path)
            const int rl0 = vr*16 + lr;          // local rows rl0, rl0+8
            const int r0  = row0 + rl0;
            const float xs0 = g_xsq[r0], xs1 = g_xsq[r0 + 8];
            float lgt[2][4];
            #pragma unroll
            for (int nf = 0; nf < 2; nf++) {
                #pragma unroll
                for (int u = 0; u < 2; u++) {
                    int cidx = vc*16 + nf*8 + lc*2 + u;
                    float cs = s_csq[cidx];
                    float d20 = xs0 + cs - 2.f * dacc[nf][u];
                    float d21 = xs1 + cs - 2.f * dacc[nf][2+u];
                    lgt[0][nf*2+u] = -2.f * sqrtf(fmaxf(d20, 0.f));
                    lgt[1][nf*2+u] = -2.f * sqrtf(fmaxf(d21, 0.f));
                }
            }
            float mx0 = fmaxf(fmaxf(lgt[0][0], lgt[0][1]), fmaxf(lgt[0][2], lgt[0][3]));
            float mx1 = fmaxf(fmaxf(lgt[1][0], lgt[1][1]), fmaxf(lgt[1][2], lgt[1][3]));
            mx0 = fmaxf(mx0, __shfl_xor_sync(0xffffffffu, mx0, 1));
            mx0 = fmaxf(mx0, __shfl_xor_sync(0xffffffffu, mx0, 2));
            mx1 = fmaxf(mx1, __shfl_xor_sync(0xffffffffu, mx1, 1));
            mx1 = fmaxf(mx1, __shfl_xor_sync(0xffffffffu, mx1, 2));
            if (lc == 0) { s_m[rl0][vc] = mx0; s_m[rl0 + 8][vc] = mx1; }
            __syncthreads();
            float M0 = fmaxf(fmaxf(s_m[rl0][0], s_m[rl0][1]), fmaxf(s_m[rl0][2], s_m[rl0][3]));
            float M1 = fmaxf(fmaxf(s_m[rl0+8][0], s_m[rl0+8][1]), fmaxf(s_m[rl0+8][2], s_m[rl0+8][3]));
            float ev[2][4];
            float ps0 = 0.f, ps1 = 0.f;
            #pragma unroll
            for (int j = 0; j < 4; j++) {
                ev[0][j] = expf(lgt[0][j] - M0); ps0 += ev[0][j];
                ev[1][j] = expf(lgt[1][j] - M1); ps1 += ev[1][j];
            }
            ps0 += __shfl_xor_sync(0xffffffffu, ps0, 1);
            ps0 += __shfl_xor_sync(0xffffffffu, ps0, 2);
            ps1 += __shfl_xor_sync(0xffffffffu, ps1, 1);
            ps1 += __shfl_xor_sync(0xffffffffu, ps1, 2);
            if (lc == 0) { s_s[rl0][vc] = ps0; s_s[rl0 + 8][vc] = ps1; }
            __syncthreads();
            float S0 = s_s[rl0][0] + s_s[rl0][1] + s_s[rl0][2] + s_s[rl0][3];
            float S1 = s_s[rl0+8][0] + s_s[rl0+8][1] + s_s[rl0+8][2] + s_s[rl0+8][3];
            float av[2][4];
            #pragma unroll
            for (int j = 0; j < 4; j++) { av[0][j] = ev[0][j] / S0; av[1][j] = ev[1][j] / S1; }
            #pragma unroll
            for (int nf = 0; nf < 2; nf++) {
                int cidx = vc*16 + nf*8 + lc*2;
                *(float2*)&outA[(size_t)r0 * KCL + cidx]       = make_float2(av[0][nf*2], av[0][nf*2+1]);
                *(float2*)&outA[(size_t)(r0 + 8) * KCL + cidx] = make_float2(av[1][nf*2], av[1][nf*2+1]);
            }
            // asum partials: sum over 32 rows of this block, per col
            float vsum[4];
            #pragma unroll
            for (int j = 0; j < 4; j++) {
                float v = av[0][j] + av[1][j];
                v += __shfl_xor_sync(0xffffffffu, v, 4);
                v += __shfl_xor_sync(0xffffffffu, v, 8);
                v += __shfl_xor_sync(0xffffffffu, v, 16);
                vsum[j] = v;
            }
            if (lr == 0) {
                #pragma unroll
                for (int nf = 0; nf < 2; nf++) {
                    s_as[vc*16 + nf*8 + lc*2][vr]     = vsum[nf*2];
                    s_as[vc*16 + nf*8 + lc*2 + 1][vr] = vsum[nf*2+1];
                }
            }
            __syncthreads();
            if (t < 64) g_asum_part[b * 64 + t] = s_as[t][0] + s_as[t][1];
        }
        if (it == 100) break;
        gridbar();

        // ---- phase B: a^T X via 3xTF32 mma (96 tiles: 6 e-blocks x 16 n-chunks) ----
        if (b < 96) {
            const int eb = b % 6;
            const int cb = b / 6;
            float* bAh = dsm;                    // [32][68]  (a chunk, [n][k])
            float* bAl = dsm + 32*68;
            float* bXh = dsm + 2*32*68;          // [32][132] (X chunk, [n][e])
            float* bXl = dsm + 2*32*68 + 32*132;
            const int wr = w >> 1, wc = w & 1;   // 4 warp-rows (k) x 2 warp-cols (e)

            float acc[8][4] = {};
            const int rn = t >> 3;
            const int acc8 = (t & 7) << 3;
            const int xc16 = (t & 7) << 4;
            float4 pa0, pa1;
            float4 qXh[4], qXl[4];

            auto loadB = [&](int ns) {
                const int n0g = cb*256 + ns*32;
                pa0 = *(const float4*)&outA[(size_t)(n0g + rn) * KCL + acc8];
                pa1 = *(const float4*)&outA[(size_t)(n0g + rn) * KCL + acc8 + 4];
                size_t gx = (size_t)(n0g + rn) * EMB + eb*128 + xc16;
                #pragma unroll
                for (int i = 0; i < 4; i++) {
                    qXh[i] = *(const float4*)&g_Xhi[gx + i*4];
                    qXl[i] = *(const float4*)&g_Xlo[gx + i*4];
                }
            };
            auto storeB = [&]() {
                float h;
                float* ph = &bAh[rn*68 + acc8];
                float* pl = &bAl[rn*68 + acc8];
                h = tf32r(pa0.x); ph[0] = h; pl[0] = tf32r(pa0.x - h);
                h = tf32r(pa0.y); ph[1] = h; pl[1] = tf32r(pa0.y - h);
                h = tf32r(pa0.z); ph[2] = h; pl[2] = tf32r(pa0.z - h);
                h = tf32r(pa0.w); ph[3] = h; pl[3] = tf32r(pa0.w - h);
                h = tf32r(pa1.x); ph[4] = h; pl[4] = tf32r(pa1.x - h);
                h = tf32r(pa1.y); ph[5] = h; pl[5] = tf32r(pa1.y - h);
                h = tf32r(pa1.z); ph[6] = h; pl[6] = tf32r(pa1.z - h);
                h = tf32r(pa1.w); ph[7] = h; pl[7] = tf32r(pa1.w - h);
                #pragma unroll
                for (int i = 0; i < 4; i++) {
                    *(float4*)&bXh[rn*132 + xc16 + i*4] = qXh[i];
                    *(float4*)&bXl[rn*132 + xc16 + i*4] = qXl[i];
                }
            };

            loadB(0); storeB();
            __syncthreads();
            for (int ns = 0; ns < 8; ns++) {
                const bool more = (ns + 1 < 8);
                if (more) loadB(ns + 1);
                #pragma unroll
                for (int kk = 0; kk < 4; kk++) {
                    const int n0 = kk * 8;
                    uint32_t ah[4], al[4];
                    const int k0 = wr * 16;
                    ah[0] = fu(bAh[(n0+lc)*68 + k0+lr]);
                    ah[1] = fu(bAh[(n0+lc)*68 + k0+lr+8]);
                    ah[2] = fu(bAh[(n0+lc+4)*68 + k0+lr]);
                    ah[3] = fu(bAh[(n0+lc+4)*68 + k0+lr+8]);
                    al[0] = fu(bAl[(n0+lc)*68 + k0+lr]);
                    al[1] = fu(bAl[(n0+lc)*68 + k0+lr+8]);
                    al[2] = fu(bAl[(n0+lc+4)*68 + k0+lr]);
                    al[3] = fu(bAl[(n0+lc+4)*68 + k0+lr+8]);
                    #pragma unroll
                    for (int nf = 0; nf < 8; nf++) {
                        const int e0 = wc*64 + nf*8;
                        uint32_t bh[2], bl[2];
                        bh[0] = fu(bXh[(n0+lc)*132 + e0+lr]);
                        bh[1] = fu(bXh[(n0+lc+4)*132 + e0+lr]);
                        bl[0] = fu(bXl[(n0+lc)*132 + e0+lr]);
                        bl[1] = fu(bXl[(n0+lc+4)*132 + e0+lr]);
                        mma_tf32(acc[nf], ah, bh);
                        mma_tf32(acc[nf], ah, bl);
                        mma_tf32(acc[nf], al, bh);
                    }
                }
                __syncthreads();            // done reading smem
                if (more) {
                    storeB();
                    __syncthreads();        // smem ready
                }
            }
            // store partials
            #pragma unroll
            for (int nf = 0; nf < 8; nf++) {
                const int kk0 = wr*16 + lr;
                const int ee  = eb*128 + wc*64 + nf*8 + lc*2;
                size_t base = (size_t)cb * (KCL*EMB) + (size_t)kk0 * EMB + ee;
                *(float2*)&g_Cpart[base]           = make_float2(acc[nf][0], acc[nf][1]);
                *(float2*)&g_Cpart[base + 8*EMB]   = make_float2(acc[nf][2], acc[nf][3]);
            }
        }
        gridbar();

        // ---- phase C: finalize (16 partials) + C hi/lo regen; fused diff/csq sums ----
        for (int c = b; c < 192; c += NB) {
            const int k = c / 3;
            const int i = c * 256 + t;
            float part = (t < 128) ? g_asum_part[t * 64 + k] : 0.f;
            float asum = blockSum<8>(part, red) + DKMEPS;
            float s = 0.f;
            #pragma unroll
            for (int p = 0; p < 16; p++) s += g_Cpart[(size_t)p * (KCL*EMB) + i];
            float cn = s / asum;
            float old = outC[i];
            g_Cprev[i] = old;
            outC[i] = cn;
            float hi = tf32r(cn);
            g_Chi[i] = hi;
            g_Clo[i] = tf32r(cn - hi);
            float2 dq = blockSum2(fabsf(cn - old), cn * cn, red2);
            if (t == 0) { g_diffp[c] = dq.x; g_csqp[c] = dq.y; }
        }
        gridbar();
    }
}

// ---------------- host ----------------
extern "C" void kernel_launch(void* const* d_in, const int* in_sizes, int n_in,
                              void* d_out, int out_size)
{
    const float* x0     = (const float*)d_in[0];
    const float* fc1_w  = (const float*)d_in[1];
    const float* fc1_b  = (const float*)d_in[2];
    const float* fc2_w  = (const float*)d_in[3];
    const float* fc2_b  = (const float*)d_in[4];
    const float* inp_w  = (const float*)d_in[5];
    const float* inp_b  = (const float*)d_in[6];
    const float* out_w  = (const float*)d_in[7];
    const float* out_b  = (const float*)d_in[8];
    const float* ln_g   = (const float*)d_in[9];
    const float* ln_b   = (const float*)d_in[10];
    const int*   iidx   = (const int*)d_in[11];

    float* outC = (float*)d_out;              // [64, 768]
    float* outA = (float*)d_out + KCL * EMB;  // [4096, 64]

    void *pA, *pQ, *pB;
    cudaGetSymbolAddress(&pA, g_bufA);
    cudaGetSymbolAddress(&pQ, g_QKV);
    cudaGetSymbolAddress(&pB, g_bufB);
    float* bufA = (float*)pA;
    float* qkv  = (float*)pQ;
    float* bufB = (float*)pB;

    cudaFuncSetAttribute(flashm, cudaFuncAttributeMaxDynamicSharedMemorySize, FLM_SMEM);
    cudaFuncSetAttribute(tgemm<true >, cudaFuncAttributeMaxDynamicSharedMemorySize, TG_SMEM);
    cudaFuncSetAttribute(tgemm<false>, cudaFuncAttributeMaxDynamicSharedMemorySize, TG_SMEM);
    cudaFuncSetAttribute(dkm_persist, cudaFuncAttributeMaxDynamicSharedMemorySize, DKM_SMEM);

    // ---- transform (tensor-core tf32) ----
    tgemm<true ><<<dim3(EMB/64,  NPTS/128), 256, TG_SMEM>>>(x0,   fc1_w, fc1_b, bufA, EMB,  EMB);
    tgemm<false><<<dim3(QKVW/64, NPTS/128), 256, TG_SMEM>>>(bufA, inp_w, inp_b, qkv,  QKVW, EMB);
    flashm<<<dim3(32, 12), 256, FLM_SMEM>>>(qkv, bufB);
    tgemm<false><<<dim3(EMB/64, NPTS/128), 256, TG_SMEM>>>(bufB, out_w, out_b, bufA, EMB, EMB);
    tgemm<true ><<<dim3(EMB/64, NPTS/128), 256, TG_SMEM>>>(bufA, fc2_w, fc2_b, bufB, EMB, EMB);
    ln_kernel<<<NPTS, 256>>>(x0, bufB, ln_g, ln_b);

    // ---- DKM: entire loop in one persistent kernel (3xTF32 mma inside) ----
    dkm_persist<<<NB, 256, DKM_SMEM>>>(iidx, outC, outA);
}

// round 16
// speedup vs baseline: 1.0518x; 1.0518x over previous
#include <cuda_runtime.h>
#include <cstdint>

#define NPTS   4096
#define EMB    768
#define QKVW   2304
#define KCL    64
#define THRESH 1e-4f
#define DKMEPS 1e-6f
#define LNEPS  1e-5f
#define NB     148      // persistent grid size (<= SM count, 1 CTA/SM guaranteed)

#define LOG2E  1.44269504088896f

// ---------------- scratch (static device globals; no allocation) ----------------
__device__ float g_bufA[NPTS * EMB];
__device__ float g_QKV [NPTS * QKVW];
__device__ float g_bufB[NPTS * EMB];
__device__ float g_X   [NPTS * EMB];
__device__ float g_xsq [NPTS];
__device__ float g_Cprev[KCL * EMB];
__device__ float g_Cpart[16 * KCL * EMB];     // split-N partials of a^T X
__device__ float g_asum_part[128 * KCL];      // per-assign-tile partials of sum_n a[n,k]
__device__ float g_csqp[192];                 // per-chunk partials of |c_k|^2
__device__ float g_diffp[192];                // per-chunk partials of sum|dC|
__device__ unsigned g_bar_gen;
__device__ unsigned g_bar_cnt;

// ---------------- FMA-pipe exp2 (no MUFU): deg-6 poly, ~1e-7 rel ----------------
__device__ __forceinline__ float exp2p(float x) {
    x = fmaxf(x, -120.f);
    float t  = x + 12582912.f;                  // 1.5*2^23
    int   ei = __float_as_int(t);
    float xi = t - 12582912.f;
    float f  = x - xi;                          // [-0.5, 0.5]
    float p  = 1.53996129e-4f;
    p = fmaf(p, f, 1.33335581e-3f);
    p = fmaf(p, f, 9.61812910e-3f);
    p = fmaf(p, f, 5.55041086e-2f);
    p = fmaf(p, f, 2.40226512e-1f);
    p = fmaf(p, f, 6.93147182e-1f);
    p = fmaf(p, f, 1.0f);
    float s = __int_as_float((ei + 127) << 23);
    return p * s;
}

// ---------------- tf32 helpers ----------------
__device__ __forceinline__ uint32_t f2tf32(float f) {
    uint32_t u;
    asm("cvt.rna.tf32.f32 %0, %1;" : "=r"(u) : "f"(f));
    return u;
}
__device__ __forceinline__ float tf32r(float f) {
    return __uint_as_float(f2tf32(f));
}
__device__ __forceinline__ uint32_t fu(float f) { return __float_as_uint(f); }
__device__ __forceinline__ void mma_tf32(float* d, const uint32_t* a, const uint32_t* b) {
    asm volatile(
        "mma.sync.aligned.m16n8k8.row.col.f32.tf32.tf32.f32 "
        "{%0,%1,%2,%3}, {%4,%5,%6,%7}, {%8,%9}, {%0,%1,%2,%3};"
        : "+f"(d[0]), "+f"(d[1]), "+f"(d[2]), "+f"(d[3])
        : "r"(a[0]), "r"(a[1]), "r"(a[2]), "r"(a[3]), "r"(b[0]), "r"(b[1]));
}
// decompose fp32 float4 -> tf32 hi/lo float4 (bit-identical to precomputed split)
__device__ __forceinline__ void split4(const float4 v, float4& h, float4& l) {
    h.x = tf32r(v.x); l.x = tf32r(v.x - h.x);
    h.y = tf32r(v.y); l.y = tf32r(v.y - h.y);
    h.z = tf32r(v.z); l.z = tf32r(v.z - h.z);
    h.w = tf32r(v.w); l.w = tf32r(v.w - h.w);
}

// ---------------- helpers ----------------
template<int NW>
__device__ __forceinline__ float blockSum(float v, float* red) {
    #pragma unroll
    for (int o = 16; o; o >>= 1) v += __shfl_xor_sync(0xffffffffu, v, o);
    int t = threadIdx.x;
    if ((t & 31) == 0) red[t >> 5] = v;
    __syncthreads();
    float s = 0.f;
    #pragma unroll
    for (int w = 0; w < NW; w++) s += red[w];
    __syncthreads();
    return s;
}

// two-channel block sum; per-channel arithmetic order identical to blockSum<8>
__device__ __forceinline__ float2 blockSum2(float a, float b, float2* red2) {
    #pragma unroll
    for (int o = 16; o; o >>= 1) {
        a += __shfl_xor_sync(0xffffffffu, a, o);
        b += __shfl_xor_sync(0xffffffffu, b, o);
    }
    int t = threadIdx.x;
    if ((t & 31) == 0) red2[t >> 5] = make_float2(a, b);
    __syncthreads();
    float sa = 0.f, sb = 0.f;
    #pragma unroll
    for (int w = 0; w < 8; w++) { sa += red2[w].x; sb += red2[w].y; }
    __syncthreads();
    return make_float2(sa, sb);
}

// sense-reversing grid barrier; safe because grid == NB and all CTAs resident
__device__ __forceinline__ void gridbar() {
    __syncthreads();
    if (threadIdx.x == 0) {
        unsigned gen = *(volatile unsigned*)&g_bar_gen;
        __threadfence();
        if (atomicAdd(&g_bar_cnt, 1u) == NB - 1) {
            g_bar_cnt = 0;
            __threadfence();
            *(volatile unsigned*)&g_bar_gen = gen + 1;
        } else {
            while (*(volatile unsigned*)&g_bar_gen == gen) { __nanosleep(32); }
        }
        __threadfence();
    }
    __syncthreads();
}

// ======== tensor-core GEMM (tf32 mma): OUT[M,N] = act(A[M,K] @ W[N,K]^T + b) =======
#define TG_SMEM ((2*128*36 + 2*64*36) * 4)
template<bool RELU>
__global__ void __launch_bounds__(256) tgemm(
    const float* __restrict__ A, const float* __restrict__ W,
    const float* __restrict__ bias, float* __restrict__ OUT,
    int Nn, int Kd)
{
    extern __shared__ float smem[];
    float* sA[2] = { smem, smem + 128*36 };
    float* sB[2] = { smem + 2*128*36, smem + 2*128*36 + 64*36 };

    const int t    = threadIdx.x;
    const int lane = t & 31;
    const int wid  = t >> 5;
    const int lr   = lane >> 2;
    const int lc   = lane & 3;
    const int wr0  = (wid >> 1) * 32;
    const int wc0  = (wid & 1) * 32;
    const int row0 = blockIdx.y * 128;
    const int col0 = blockIdx.x * 64;

    float d[2][4][4] = {};
    float4 ra[4]; float4 rb[2];

    auto gload = [&](int s) {
        const int k0 = s << 5;
        #pragma unroll
        for (int i = 0; i < 4; i++) {
            int lin = t + (i << 8);
            int r = lin >> 3, c = (lin & 7) << 2;
            ra[i] = *(const float4*)&A[(size_t)(row0 + r) * Kd + k0 + c];
        }
        #pragma unroll
        for (int i = 0; i < 2; i++) {
            int lin = t + (i << 8);
            int n = lin >> 3, c = (lin & 7) << 2;
            rb[i] = *(const float4*)&W[(size_t)(col0 + n) * Kd + k0 + c];
        }
    };
    auto sstore = [&](int buf) {
        #pragma unroll
        for (int i = 0; i < 4; i++) {
            int lin = t + (i << 8);
            int r = lin >> 3, c = (lin & 7) << 2;
            float* p = &sA[buf][r * 36 + c];
            p[0] = tf32r(ra[i].x); p[1] = tf32r(ra[i].y);
            p[2] = tf32r(ra[i].z); p[3] = tf32r(ra[i].w);
        }
        #pragma unroll
        for (int i = 0; i < 2; i++) {
            int lin = t + (i << 8);
            int n = lin >> 3, c = (lin & 7) << 2;
            float* p = &sB[buf][n * 36 + c];
            p[0] = tf32r(rb[i].x); p[1] = tf32r(rb[i].y);
            p[2] = tf32r(rb[i].z); p[3] = tf32r(rb[i].w);
        }
    };

    gload(0); sstore(0);
    __syncthreads();

    const int nslab = Kd >> 5;
    for (int s = 0; s < nslab; s++) {
        const int cur = s & 1;
        const bool more = (s + 1 < nslab);
        if (more) gload(s + 1);
        #pragma unroll
        for (int ks = 0; ks < 32; ks += 8) {
            uint32_t af[2][4], bf[4][2];
            #pragma unroll
            for (int mt = 0; mt < 2; mt++) {
                const float* p = &sA[cur][(wr0 + mt*16 + lr) * 36 + ks + lc];
                af[mt][0] = fu(p[0]);
                af[mt][1] = fu(p[8*36]);
                af[mt][2] = fu(p[4]);
                af[mt][3] = fu(p[8*36 + 4]);
            }
            #pragma unroll
            for (int nt = 0; nt < 4; nt++) {
                const float* p = &sB[cur][(wc0 + nt*8 + lr) * 36 + ks + lc];
                bf[nt][0] = fu(p[0]);
                bf[nt][1] = fu(p[4]);
            }
            #pragma unroll
            for (int mt = 0; mt < 2; mt++)
                #pragma unroll
                for (int nt = 0; nt < 4; nt++)
                    mma_tf32(d[mt][nt], af[mt], bf[nt]);
        }
        if (more) {
            sstore(cur ^ 1);
            __syncthreads();
        }
    }

    #pragma unroll
    for (int mt = 0; mt < 2; mt++) {
        #pragma unroll
        for (int nt = 0; nt < 4; nt++) {
            int r0 = row0 + wr0 + mt*16 + lr;
            int c0 = col0 + wc0 + nt*8 + (lc << 1);
            float b0 = bias[c0], b1 = bias[c0 + 1];
            float v0 = d[mt][nt][0] + b0, v1 = d[mt][nt][1] + b1;
            float v2 = d[mt][nt][2] + b0, v3 = d[mt][nt][3] + b1;
            if (RELU) {
                v0 = fmaxf(v0, 0.f); v1 = fmaxf(v1, 0.f);
                v2 = fmaxf(v2, 0.f); v3 = fmaxf(v3, 0.f);
            }
            *(float2*)&OUT[(size_t)r0 * Nn + c0]       = make_float2(v0, v1);
            *(float2*)&OUT[(size_t)(r0 + 8) * Nn + c0] = make_float2(v2, v3);
        }
    }
}

// ========== flash attention mma: Q-tile 128, K-tile 128, hd=64, tf32 tensor =========
#define FLM_SMEM ((128*68 + 128*68 + 128*72 + 128*132) * 4)
__global__ void __launch_bounds__(256) flashm(
    const float* __restrict__ QKV, float* __restrict__ O)
{
    extern __shared__ float sm[];
    float* sQ = sm;                  // [q=128][d=64] stride 68 (tf32)
    float* sK = sQ + 128*68;         // [c=128][d=64] stride 68 (tf32)
    float* sV = sK + 128*68;         // [c=128][d=64] stride 72 (tf32)
    float* sP = sV + 128*72;         // [q=128][c=128] stride 132 (tf32)
    const int t    = threadIdx.x;
    const int lane = t & 31;
    const int w    = t >> 5;
    const int lr   = lane >> 2;
    const int lc   = lane & 3;
    const int qb   = blockIdx.x, h = blockIdx.y;
    const int q0   = w * 16;
    const float SC2 = 0.125f * LOG2E;

    {
        int r = t >> 1, half = t & 1;
        #pragma unroll
        for (int p = 0; p < 8; p++) {
            int d = half*32 + p*4;
            float4 q = *(const float4*)&QKV[(size_t)(qb*128 + r) * QKVW + h*64 + d];
            float* dq = &sQ[r*68 + d];
            dq[0] = tf32r(q.x); dq[1] = tf32r(q.y); dq[2] = tf32r(q.z); dq[3] = tf32r(q.w);
        }
    }

    float oacc[8][4] = {};
    float m[2] = {-1e30f, -1e30f}, l[2] = {0.f, 0.f};

    for (int kb = 0; kb < 32; kb++) {
        {
            int r = t >> 1, half = t & 1;
            #pragma unroll
            for (int p = 0; p < 8; p++) {
                int d = half*32 + p*4;
                float4 kv = *(const float4*)&QKV[(size_t)(kb*128 + r) * QKVW + 768 + h*64 + d];
                float* dk = &sK[r*68 + d];
                dk[0] = tf32r(kv.x); dk[1] = tf32r(kv.y); dk[2] = tf32r(kv.z); dk[3] = tf32r(kv.w);
                float4 vv = *(const float4*)&QKV[(size_t)(kb*128 + r) * QKVW + 1536 + h*64 + d];
                float* dv = &sV[r*72 + d];
                dv[0] = tf32r(vv.x); dv[1] = tf32r(vv.y); dv[2] = tf32r(vv.z); dv[3] = tf32r(vv.w);
            }
        }
        __syncthreads();

        float sacc[16][4] = {};
        #pragma unroll
        for (int kk = 0; kk < 8; kk++) {
            const int k0 = kk * 8;
            uint32_t a[4];
            const float* pa = &sQ[(q0 + lr)*68 + k0 + lc];
            a[0] = fu(pa[0]); a[1] = fu(pa[8*68]); a[2] = fu(pa[4]); a[3] = fu(pa[8*68 + 4]);
            #pragma unroll
            for (int nt = 0; nt < 16; nt++) {
                uint32_t b[2];
                const float* pb = &sK[(nt*8 + lr)*68 + k0 + lc];
                b[0] = fu(pb[0]); b[1] = fu(pb[4]);
                mma_tf32(sacc[nt], a, b);
            }
        }

        #pragma unroll
        for (int row = 0; row < 2; row++) {
            float mx = -1e30f;
            #pragma unroll
            for (int nt = 0; nt < 16; nt++) {
                sacc[nt][row*2]   *= SC2;
                sacc[nt][row*2+1] *= SC2;
                mx = fmaxf(mx, fmaxf(sacc[nt][row*2], sacc[nt][row*2+1]));
            }
            mx = fmaxf(mx, __shfl_xor_sync(0xffffffffu, mx, 1));
            mx = fmaxf(mx, __shfl_xor_sync(0xffffffffu, mx, 2));
            float mn = fmaxf(m[row], mx);
            float sc = exp2p(m[row] - mn);
            float ps = 0.f;
            #pragma unroll
            for (int nt = 0; nt < 16; nt++) {
                float e0 = exp2p(sacc[nt][row*2]   - mn);
                float e1 = exp2p(sacc[nt][row*2+1] - mn);
                sacc[nt][row*2] = e0; sacc[nt][row*2+1] = e1;
                ps += e0 + e1;
            }
            ps += __shfl_xor_sync(0xffffffffu, ps, 1);
            ps += __shfl_xor_sync(0xffffffffu, ps, 2);
            l[row] = l[row] * sc + ps;
            m[row] = mn;
            #pragma unroll
            for (int nd = 0; nd < 8; nd++) {
                oacc[nd][row*2]   *= sc;
                oacc[nd][row*2+1] *= sc;
            }
        }

        #pragma unroll
        for (int nt = 0; nt < 16; nt++) {
            int c = nt*8 + lc*2;
            *(float2*)&sP[(q0 + lr)*132 + c]     = make_float2(tf32r(sacc[nt][0]), tf32r(sacc[nt][1]));
            *(float2*)&sP[(q0 + lr + 8)*132 + c] = make_float2(tf32r(sacc[nt][2]), tf32r(sacc[nt][3]));
        }
        __syncthreads();

        #pragma unroll
        for (int kc = 0; kc < 16; kc++) {
            uint32_t a[4];
            const float* pa = &sP[(q0 + lr)*132 + kc*8 + lc];
            a[0] = fu(pa[0]); a[1] = fu(pa[8*132]); a[2] = fu(pa[4]); a[3] = fu(pa[8*132 + 4]);
            #pragma unroll
            for (int nd = 0; nd < 8; nd++) {
                uint32_t b[2];
                const float* pb = &sV[(kc*8 + lc)*72 + nd*8 + lr];
                b[0] = fu(pb[0]); b[1] = fu(pb[4*72]);
                mma_tf32(oacc[nd], a, b);
            }
        }
        __syncthreads();
    }

    const float inv0 = 1.f / l[0], inv1 = 1.f / l[1];
    #pragma unroll
    for (int nd = 0; nd < 8; nd++) {
        int r = qb*128 + q0 + lr;
        int c = h*64 + nd*8 + lc*2;
        *(float2*)&O[(size_t)r * EMB + c]       = make_float2(oacc[nd][0]*inv0, oacc[nd][1]*inv0);
        *(float2*)&O[(size_t)(r + 8) * EMB + c] = make_float2(oacc[nd][2]*inv1, oacc[nd][3]*inv1);
    }
}

// ---------------- residual + layernorm + xsq ----------------
__global__ void __launch_bounds__(256) ln_kernel(
    const float* __restrict__ x0, const float* __restrict__ y,
    const float* __restrict__ lg, const float* __restrict__ lb)
{
    __shared__ float red[8];
    int r = blockIdx.x, t = threadIdx.x;
    float z[3];
    float s = 0.f;
    #pragma unroll
    for (int i = 0; i < 3; i++) {
        int c = t + i * 256;
        z[i] = 0.5f * x0[(size_t)r * EMB + c] + 0.5f * y[(size_t)r * EMB + c];
        s += z[i];
    }
    s = blockSum<8>(s, red);
    float mu = s * (1.f / 768.f);
    float v = 0.f;
    #pragma unroll
    for (int i = 0; i < 3; i++) { float dz = z[i] - mu; v = fmaf(dz, dz, v); }
    v = blockSum<8>(v, red);
    float rstd = rsqrtf(v * (1.f / 768.f) + LNEPS);
    float q = 0.f;
    #pragma unroll
    for (int i = 0; i < 3; i++) {
        int c = t + i * 256;
        float xv = (z[i] - mu) * rstd * lg[c] + lb[c];
        g_X[(size_t)r * EMB + c] = xv;
        q = fmaf(xv, xv, q);
    }
    q = blockSum<8>(q, red);
    if (t == 0) g_xsq[r] = q;
}

// ================= persistent DKM: whole loop in ONE kernel ======================
// distances via 3xTF32 mma (err ~1e-6); hi/lo split done IN-REGISTER at staging
// (bit-identical to a precomputed split); softmax/eps/div identical to reference
#define DKM_SMEM ((2*32*68 + 2*64*68) * 4)     // 52224 B (phase A is the max)
__global__ void __launch_bounds__(256) dkm_persist(
    const int* __restrict__ idx, float* __restrict__ outC, float* __restrict__ outA)
{
    extern __shared__ float dsm[];
    __shared__ float red[8];
    __shared__ float2 red2[8];
    __shared__ float s_csq[64];
    __shared__ float s_m[32][4];
    __shared__ float s_s[32][4];
    __shared__ float s_as[64][2];

    const int b    = blockIdx.x;
    const int t    = threadIdx.x;
    const int lane = t & 31;
    const int w    = t >> 5;
    const int lr   = lane >> 2;
    const int lc   = lane & 3;

    // ---- init: gather C0 = X[idx], csq chunk partials ----
    for (int c = b; c < 192; c += NB) {
        int k = c / 3;
        int i = c * 256 + t;
        int e = i - k * EMB;
        float v = g_X[(size_t)idx[k] * EMB + e];
        outC[i] = v;
        float s = blockSum<8>(v * v, red);
        if (t == 0) g_csqp[c] = s;
    }
    gridbar();

    for (int it = 0; it <= 100; it++) {
        // ---- break check: parallel 192-way load + blockSum (identical in all blocks) ----
        if (it > 0) {
            float dv = (t < 192) ? g_diffp[t] : 0.f;
            float diff = blockSum<8>(dv, red);
            if (diff <= THRESH) {
                for (int c = b; c < 192; c += NB)
                    outC[c * 256 + t] = g_Cprev[c * 256 + t];
                return;
            }
        }

        // ---- phase A: assignments via 3xTF32 mma (blocks 0..127, 32 rows each) ----
        if (b < 128) {
            if (t < 64) s_csq[t] = g_csqp[3*t] + g_csqp[3*t+1] + g_csqp[3*t+2];
            const int row0 = b * 32;
            float* aXh = dsm;                    // [32][68]
            float* aXl = dsm + 32*68;
            float* aCh = dsm + 2*32*68;          // [64][68]
            float* aCl = dsm + 2*32*68 + 64*68;
            const int vr = w & 1, vc = w >> 1;   // 2 warp-rows x 4 warp-cols

            float dacc[2][4] = {};
            const int xr = t >> 3, xc = (t & 7) << 3;   // X: 32 rows, 8 thr/row, 8 cols each
            const int cr = t >> 2, cc = (t & 3) << 4;   // C: 64 rows, 4 thr/row, 16 cols each
            float4 pX[2], pC[4];

            auto loadA = [&](int ks) {
                size_t gx = (size_t)(row0 + xr) * EMB + ks*64 + xc;
                pX[0] = *(const float4*)&g_X[gx];
                pX[1] = *(const float4*)&g_X[gx + 4];
                size_t gc = (size_t)cr * EMB + ks*64 + cc;
                #pragma unroll
                for (int i = 0; i < 4; i++)
                    pC[i] = *(const float4*)&outC[gc + i*4];
            };
            auto storeA = [&]() {
                #pragma unroll
                for (int i = 0; i < 2; i++) {
                    float4 h, l;
                    split4(pX[i], h, l);
                    *(float4*)&aXh[xr*68 + xc + i*4] = h;
                    *(float4*)&aXl[xr*68 + xc + i*4] = l;
                }
                #pragma unroll
                for (int i = 0; i < 4; i++) {
                    float4 h, l;
                    split4(pC[i], h, l);
                    *(float4*)&aCh[cr*68 + cc + i*4] = h;
                    *(float4*)&aCl[cr*68 + cc + i*4] = l;
                }
            };

            loadA(0); storeA();
            __syncthreads();
            for (int ks = 0; ks < 12; ks++) {
                const bool more = (ks + 1 < 12);
                if (more) loadA(ks + 1);
                #pragma unroll
                for (int kk = 0; kk < 8; kk++) {
                    const int k0 = kk * 8;
                    uint32_t ah[4], al[4];
                    const float* ph = &aXh[(vr*16 + lr)*68 + k0 + lc];
                    ah[0]=fu(ph[0]); ah[1]=fu(ph[8*68]); ah[2]=fu(ph[4]); ah[3]=fu(ph[8*68+4]);
                    const float* pl = &aXl[(vr*16 + lr)*68 + k0 + lc];
                    al[0]=fu(pl[0]); al[1]=fu(pl[8*68]); al[2]=fu(pl[4]); al[3]=fu(pl[8*68+4]);
                    #pragma unroll
                    for (int nf = 0; nf < 2; nf++) {
                        uint32_t bh[2], bl[2];
                        const float* qh = &aCh[(vc*16 + nf*8 + lr)*68 + k0 + lc];
                        bh[0]=fu(qh[0]); bh[1]=fu(qh[4]);
                        const float* ql = &aCl[(vc*16 + nf*8 + lr)*68 + k0 + lc];
                        bl[0]=fu(ql[0]); bl[1]=fu(ql[4]);
                        mma_tf32(dacc[nf], ah, bh);
                        mma_tf32(dacc[nf], ah, bl);
                        mma_tf32(dacc[nf], al, bh);
                    }
                }
                __syncthreads();            // done reading smem
                if (more) {
                    storeA();
                    __syncthreads();        // smem ready
                }
            }

            // epilogue: dist + softmax (formulas identical to reference path)
            const int rl0 = vr*16 + lr;          // local rows rl0, rl0+8
            const int r0  = row0 + rl0;
            const float xs0 = g_xsq[r0], xs1 = g_xsq[r0 + 8];
            float lgt[2][4];
            #pragma unroll
            for (int nf = 0; nf < 2; nf++) {
                #pragma unroll
                for (int u = 0; u < 2; u++) {
                    int cidx = vc*16 + nf*8 + lc*2 + u;
                    float cs = s_csq[cidx];
                    float d20 = xs0 + cs - 2.f * dacc[nf][u];
                    float d21 = xs1 + cs - 2.f * dacc[nf][2+u];
                    lgt[0][nf*2+u] = -2.f * sqrtf(fmaxf(d20, 0.f));
                    lgt[1][nf*2+u] = -2.f * sqrtf(fmaxf(d21, 0.f));
                }
            }
            float mx0 = fmaxf(fmaxf(lgt[0][0], lgt[0][1]), fmaxf(lgt[0][2], lgt[0][3]));
            float mx1 = fmaxf(fmaxf(lgt[1][0], lgt[1][1]), fmaxf(lgt[1][2], lgt[1][3]));
            mx0 = fmaxf(mx0, __shfl_xor_sync(0xffffffffu, mx0, 1));
            mx0 = fmaxf(mx0, __shfl_xor_sync(0xffffffffu, mx0, 2));
            mx1 = fmaxf(mx1, __shfl_xor_sync(0xffffffffu, mx1, 1));
            mx1 = fmaxf(mx1, __shfl_xor_sync(0xffffffffu, mx1, 2));
            if (lc == 0) { s_m[rl0][vc] = mx0; s_m[rl0 + 8][vc] = mx1; }
            __syncthreads();
            float M0 = fmaxf(fmaxf(s_m[rl0][0], s_m[rl0][1]), fmaxf(s_m[rl0][2], s_m[rl0][3]));
            float M1 = fmaxf(fmaxf(s_m[rl0+8][0], s_m[rl0+8][1]), fmaxf(s_m[rl0+8][2], s_m[rl0+8][3]));
            float ev[2][4];
            float ps0 = 0.f, ps1 = 0.f;
            #pragma unroll
            for (int j = 0; j < 4; j++) {
                ev[0][j] = expf(lgt[0][j] - M0); ps0 += ev[0][j];
                ev[1][j] = expf(lgt[1][j] - M1); ps1 += ev[1][j];
            }
            ps0 += __shfl_xor_sync(0xffffffffu, ps0, 1);
            ps0 += __shfl_xor_sync(0xffffffffu, ps0, 2);
            ps1 += __shfl_xor_sync(0xffffffffu, ps1, 1);
            ps1 += __shfl_xor_sync(0xffffffffu, ps1, 2);
            if (lc == 0) { s_s[rl0][vc] = ps0; s_s[rl0 + 8][vc] = ps1; }
            __syncthreads();
            float S0 = s_s[rl0][0] + s_s[rl0][1] + s_s[rl0][2] + s_s[rl0][3];
            float S1 = s_s[rl0+8][0] + s_s[rl0+8][1] + s_s[rl0+8][2] + s_s[rl0+8][3];
            float av[2][4];
            #pragma unroll
            for (int j = 0; j < 4; j++) { av[0][j] = ev[0][j] / S0; av[1][j] = ev[1][j] / S1; }
            #pragma unroll
            for (int nf = 0; nf < 2; nf++) {
                int cidx = vc*16 + nf*8 + lc*2;
                *(float2*)&outA[(size_t)r0 * KCL + cidx]       = make_float2(av[0][nf*2], av[0][nf*2+1]);
                *(float2*)&outA[(size_t)(r0 + 8) * KCL + cidx] = make_float2(av[1][nf*2], av[1][nf*2+1]);
            }
            // asum partials: sum over 32 rows of this block, per col
            float vsum[4];
            #pragma unroll
            for (int j = 0; j < 4; j++) {
                float v = av[0][j] + av[1][j];
                v += __shfl_xor_sync(0xffffffffu, v, 4);
                v += __shfl_xor_sync(0xffffffffu, v, 8);
                v += __shfl_xor_sync(0xffffffffu, v, 16);
                vsum[j] = v;
            }
            if (lr == 0) {
                #pragma unroll
                for (int nf = 0; nf < 2; nf++) {
                    s_as[vc*16 + nf*8 + lc*2][vr]     = vsum[nf*2];
                    s_as[vc*16 + nf*8 + lc*2 + 1][vr] = vsum[nf*2+1];
                }
            }
            __syncthreads();
            if (t < 64) g_asum_part[b * 64 + t] = s_as[t][0] + s_as[t][1];
        }
        if (it == 100) break;
        gridbar();

        // ---- phase B: a^T X via 3xTF32 mma (96 tiles: 6 e-blocks x 16 n-chunks) ----
        if (b < 96) {
            const int eb = b % 6;
            const int cb = b / 6;
            float* bAh = dsm;                    // [32][68]  (a chunk, [n][k])
            float* bAl = dsm + 32*68;
            float* bXh = dsm + 2*32*68;          // [32][132] (X chunk, [n][e])
            float* bXl = dsm + 2*32*68 + 32*132;
            const int wr = w >> 1, wc = w & 1;   // 4 warp-rows (k) x 2 warp-cols (e)

            float acc[8][4] = {};
            const int rn = t >> 3;
            const int acc8 = (t & 7) << 3;
            const int xc16 = (t & 7) << 4;
            float4 pa0, pa1;
            float4 qX[4];

            auto loadB = [&](int ns) {
                const int n0g = cb*256 + ns*32;
                pa0 = *(const float4*)&outA[(size_t)(n0g + rn) * KCL + acc8];
                pa1 = *(const float4*)&outA[(size_t)(n0g + rn) * KCL + acc8 + 4];
                size_t gx = (size_t)(n0g + rn) * EMB + eb*128 + xc16;
                #pragma unroll
                for (int i = 0; i < 4; i++)
                    qX[i] = *(const float4*)&g_X[gx + i*4];
            };
            auto storeB = [&]() {
                float4 h, l;
                split4(pa0, h, l);
                *(float4*)&bAh[rn*68 + acc8] = h;
                *(float4*)&bAl[rn*68 + acc8] = l;
                split4(pa1, h, l);
                *(float4*)&bAh[rn*68 + acc8 + 4] = h;
                *(float4*)&bAl[rn*68 + acc8 + 4] = l;
                #pragma unroll
                for (int i = 0; i < 4; i++) {
                    split4(qX[i], h, l);
                    *(float4*)&bXh[rn*132 + xc16 + i*4] = h;
                    *(float4*)&bXl[rn*132 + xc16 + i*4] = l;
                }
            };

            loadB(0); storeB();
            __syncthreads();
            for (int ns = 0; ns < 8; ns++) {
                const bool more = (ns + 1 < 8);
                if (more) loadB(ns + 1);
                #pragma unroll
                for (int kk = 0; kk < 4; kk++) {
                    const int n0 = kk * 8;
                    uint32_t ah[4], al[4];
                    const int k0 = wr * 16;
                    ah[0] = fu(bAh[(n0+lc)*68 + k0+lr]);
                    ah[1] = fu(bAh[(n0+lc)*68 + k0+lr+8]);
                    ah[2] = fu(bAh[(n0+lc+4)*68 + k0+lr]);
                    ah[3] = fu(bAh[(n0+lc+4)*68 + k0+lr+8]);
                    al[0] = fu(bAl[(n0+lc)*68 + k0+lr]);
                    al[1] = fu(bAl[(n0+lc)*68 + k0+lr+8]);
                    al[2] = fu(bAl[(n0+lc+4)*68 + k0+lr]);
                    al[3] = fu(bAl[(n0+lc+4)*68 + k0+lr+8]);
                    #pragma unroll
                    for (int nf = 0; nf < 8; nf++) {
                        const int e0 = wc*64 + nf*8;
                        uint32_t bh[2], bl[2];
                        bh[0] = fu(bXh[(n0+lc)*132 + e0+lr]);
                        bh[1] = fu(bXh[(n0+lc+4)*132 + e0+lr]);
                        bl[0] = fu(bXl[(n0+lc)*132 + e0+lr]);
                        bl[1] = fu(bXl[(n0+lc+4)*132 + e0+lr]);
                        mma_tf32(acc[nf], ah, bh);
                        mma_tf32(acc[nf], ah, bl);
                        mma_tf32(acc[nf], al, bh);
                    }
                }
                __syncthreads();            // done reading smem
                if (more) {
                    storeB();
                    __syncthreads();        // smem ready
                }
            }
            // store partials
            #pragma unroll
            for (int nf = 0; nf < 8; nf++) {
                const int kk0 = wr*16 + lr;
                const int ee  = eb*128 + wc*64 + nf*8 + lc*2;
                size_t base = (size_t)cb * (KCL*EMB) + (size_t)kk0 * EMB + ee;
                *(float2*)&g_Cpart[base]           = make_float2(acc[nf][0], acc[nf][1]);
                *(float2*)&g_Cpart[base + 8*EMB]   = make_float2(acc[nf][2], acc[nf][3]);
            }
        }
        gridbar();

        // ---- phase C: finalize (16 partials); fused diff/csq sums ----
        for (int c = b; c < 192; c += NB) {
            const int k = c / 3;
            const int i = c * 256 + t;
            float part = (t < 128) ? g_asum_part[t * 64 + k] : 0.f;
            float asum = blockSum<8>(part, red) + DKMEPS;
            float s = 0.f;
            #pragma unroll
            for (int p = 0; p < 16; p++) s += g_Cpart[(size_t)p * (KCL*EMB) + i];
            float cn = s / asum;
            float old = outC[i];
            g_Cprev[i] = old;
            outC[i] = cn;
            float2 dq = blockSum2(fabsf(cn - old), cn * cn, red2);
            if (t == 0) { g_diffp[c] = dq.x; g_csqp[c] = dq.y; }
        }
        gridbar();
    }
}

// ---------------- host ----------------
extern "C" void kernel_launch(void* const* d_in, const int* in_sizes, int n_in,
                              void* d_out, int out_size)
{
    const float* x0     = (const float*)d_in[0];
    const float* fc1_w  = (const float*)d_in[1];
    const float* fc1_b  = (const float*)d_in[2];
    const float* fc2_w  = (const float*)d_in[3];
    const float* fc2_b  = (const float*)d_in[4];
    const float* inp_w  = (const float*)d_in[5];
    const float* inp_b  = (const float*)d_in[6];
    const float* out_w  = (const float*)d_in[7];
    const float* out_b  = (const float*)d_in[8];
    const float* ln_g   = (const float*)d_in[9];
    const float* ln_b   = (const float*)d_in[10];
    const int*   iidx   = (const int*)d_in[11];

    float* outC = (float*)d_out;              // [64, 768]
    float* outA = (float*)d_out + KCL * EMB;  // [4096, 64]

    void *pA, *pQ, *pB;
    cudaGetSymbolAddress(&pA, g_bufA);
    cudaGetSymbolAddress(&pQ, g_QKV);
    cudaGetSymbolAddress(&pB, g_bufB);
    float* bufA = (float*)pA;
    float* qkv  = (float*)pQ;
    float* bufB = (float*)pB;

    cudaFuncSetAttribute(flashm, cudaFuncAttributeMaxDynamicSharedMemorySize, FLM_SMEM);
    cudaFuncSetAttribute(tgemm<true >, cudaFuncAttributeMaxDynamicSharedMemorySize, TG_SMEM);
    cudaFuncSetAttribute(tgemm<false>, cudaFuncAttributeMaxDynamicSharedMemorySize, TG_SMEM);
    cudaFuncSetAttribute(dkm_persist, cudaFuncAttributeMaxDynamicSharedMemorySize, DKM_SMEM);

    // ---- transform (tensor-core tf32) ----
    tgemm<true ><<<dim3(EMB/64,  NPTS/128), 256, TG_SMEM>>>(x0,   fc1_w, fc1_b, bufA, EMB,  EMB);
    tgemm<false><<<dim3(QKVW/64, NPTS/128), 256, TG_SMEM>>>(bufA, inp_w, inp_b, qkv,  QKVW, EMB);
    flashm<<<dim3(32, 12), 256, FLM_SMEM>>>(qkv, bufB);
    tgemm<false><<<dim3(EMB/64, NPTS/128), 256, TG_SMEM>>>(bufB, out_w, out_b, bufA, EMB, EMB);
    tgemm<true ><<<dim3(EMB/64, NPTS/128), 256, TG_SMEM>>>(bufA, fc2_w, fc2_b, bufB, EMB, EMB);
    ln_kernel<<<NPTS, 256>>>(x0, bufB, ln_g, ln_b);

    // ---- DKM: entire loop in one persistent kernel (3xTF32 mma inside) ----
    dkm_persist<<<NB, 256, DKM_SMEM>>>(iidx, outC, outA);
}